// round 13
// baseline (speedup 1.0000x reference)
#include <cuda_runtime.h>
#include <cuda_bf16.h>
#include <cuda_fp16.h>
#include <stdint.h>

#define BHW   4096
#define CCH   256
#define NBAT  4
#define NTOK  16384
#define NGRP  32
#define GELEMS (8*BHW)
#define OUT_MAIN ((size_t)NBAT*CCH*BHW)

#define FITERS 128
// flash smem BYTE offsets
#define QB    0                     /* Q fp16 [64][264]   33792 B */
#define KB(i) (33792 + (i)*16896)   /* K fp16 [32][264] x2        */
#define VB(j) (67584 + (j)*16896)   /* V u32  [16][264] x2        */
#define SLB   101376                /* l[64] fp32                 */
#define FSMEM 101664

__device__ __half   g_th[(size_t)NTOK*CCH];
__device__ __half   g_qkh[(size_t)NTOK*512];
__device__ unsigned g_vp[(size_t)(NTOK/2)*256];
__device__ __half   g_oh[(size_t)NTOK*CCH];
__device__ __half   g_wh[(size_t)1024*256];
__device__ float    g_u[NTOK];
__device__ float    g_mu[NBAT*NGRP];
__device__ float    g_rs[NBAT*NGRP];

__device__ __forceinline__ void mma_f16(float* c, const unsigned* a, unsigned b0, unsigned b1) {
    asm volatile("mma.sync.aligned.m16n8k16.row.col.f32.f16.f16.f32 "
                 "{%0,%1,%2,%3}, {%4,%5,%6,%7}, {%8,%9}, {%0,%1,%2,%3};"
                 : "+f"(c[0]), "+f"(c[1]), "+f"(c[2]), "+f"(c[3])
                 : "r"(a[0]), "r"(a[1]), "r"(a[2]), "r"(a[3]), "r"(b0), "r"(b1));
}
__device__ __forceinline__ void mma_bf16(float* c, const unsigned* a, unsigned b0, unsigned b1) {
    asm volatile("mma.sync.aligned.m16n8k16.row.col.f32.bf16.bf16.f32 "
                 "{%0,%1,%2,%3}, {%4,%5,%6,%7}, {%8,%9}, {%0,%1,%2,%3};"
                 : "+f"(c[0]), "+f"(c[1]), "+f"(c[2]), "+f"(c[3])
                 : "r"(a[0]), "r"(a[1]), "r"(a[2]), "r"(a[3]), "r"(b0), "r"(b1));
}
__device__ __forceinline__ void ldm4(unsigned& r0, unsigned& r1, unsigned& r2, unsigned& r3,
                                     uint32_t addr) {
    asm volatile("ldmatrix.sync.aligned.m8n8.x4.shared.b16 {%0,%1,%2,%3}, [%4];"
                 : "=r"(r0), "=r"(r1), "=r"(r2), "=r"(r3) : "r"(addr));
}
__device__ __forceinline__ uint32_t smem_u32(const void* p) {
    uint32_t a;
    asm("{ .reg .u64 t; cvta.to.shared.u64 t, %1; cvt.u32.u64 %0, t; }" : "=r"(a) : "l"(p));
    return a;
}
__device__ __forceinline__ void cp16(uint32_t saddr, const void* g) {
    asm volatile("cp.async.cg.shared.global [%0], [%1], 16;" :: "r"(saddr), "l"(g));
}
#define CP_COMMIT asm volatile("cp.async.commit_group;" ::: "memory")
#define CP_WAIT0  asm volatile("cp.async.wait_group 0;" ::: "memory")
__device__ __forceinline__ unsigned pack_bf(float lo, float hi) {
    unsigned r;
    asm("cvt.rn.bf16x2.f32 %0, %1, %2;" : "=r"(r) : "f"(hi), "f"(lo));
    return r;
}

// ---------------- GroupNorm --------------------------------------------------
__global__ void gn_stats(const float* __restrict__ x) {
    int bg = blockIdx.x;
    const float4* p = (const float4*)(x + (size_t)bg * GELEMS);
    float s = 0.f, ss = 0.f;
    for (int i = threadIdx.x; i < GELEMS/4; i += blockDim.x) {
        float4 v = p[i];
        s += v.x + v.y + v.z + v.w;
        ss += v.x*v.x + v.y*v.y + v.z*v.z + v.w*v.w;
    }
    __shared__ float rs[8], rss[8];
    #pragma unroll
    for (int o = 16; o; o >>= 1) { s += __shfl_down_sync(~0u, s, o); ss += __shfl_down_sync(~0u, ss, o); }
    if ((threadIdx.x & 31) == 0) { rs[threadIdx.x >> 5] = s; rss[threadIdx.x >> 5] = ss; }
    __syncthreads();
    if (threadIdx.x < 32) {
        s  = (threadIdx.x < 8) ? rs[threadIdx.x]  : 0.f;
        ss = (threadIdx.x < 8) ? rss[threadIdx.x] : 0.f;
        #pragma unroll
        for (int o = 4; o; o >>= 1) { s += __shfl_down_sync(~0u, s, o); ss += __shfl_down_sync(~0u, ss, o); }
        if (threadIdx.x == 0) {
            float mu = s / (float)GELEMS;
            float var = ss / (float)GELEMS - mu * mu;
            g_mu[bg] = mu; g_rs[bg] = rsqrtf(var + 1e-6f);
        }
    }
}

__global__ void gn_apply(const float* __restrict__ x, const float* __restrict__ gamma,
                         const float* __restrict__ beta) {
    __shared__ float tile[32][33];
    int b = blockIdx.z, c0 = blockIdx.y * 32, s0 = blockIdx.x * 32;
    int tx = threadIdx.x, ty = threadIdx.y;
    for (int i = ty; i < 32; i += 8) {
        int c = c0 + i, bg = b * NGRP + (c >> 3);
        float v = x[((size_t)(b * CCH + c)) * BHW + s0 + tx];
        tile[i][tx] = (v - g_mu[bg]) * g_rs[bg] * gamma[c] + beta[c];
    }
    __syncthreads();
    for (int i = ty; i < 32; i += 8)
        g_th[((size_t)(b * BHW + s0 + i)) * CCH + c0 + tx] = __float2half(tile[tx][i]);
}

// ---------------- weight pack to fp16 ----------------------------------------
__global__ void w_pack(const float* __restrict__ wq, const float* __restrict__ wk,
                       const float* __restrict__ wv, const float* __restrict__ wp) {
    int r = blockIdx.x, tid = threadIdx.x;
    const float* w = (r < 256) ? wq : (r < 512) ? wk : (r < 768) ? wv : wp;
    g_wh[(size_t)r * 256 + tid] = __float2half(w[(size_t)(r & 255) * 256 + tid]);
}

// ---------------- fp16 gemm core (K=256) -------------------------------------
__device__ __forceinline__ void gemm_core_h(const __half* A, const __half* B, int m0,
                                            __half* As, __half* Bs, float acc[2][8][4]) {
    const int tid = threadIdx.x, lane = tid & 31, warp = tid >> 5;
    const int wm = warp >> 1, wn = warp & 1, g = lane >> 2, t4 = lane & 3;
    #pragma unroll
    for (int mi = 0; mi < 2; mi++)
        #pragma unroll
        for (int ni = 0; ni < 8; ni++)
            #pragma unroll
            for (int e = 0; e < 4; e++) acc[mi][ni][e] = 0.f;
    for (int kc = 0; kc < 256; kc += 32) {
        #pragma unroll
        for (int it = 0; it < 2; it++) {
            int idx = tid + it * 256, row = idx >> 2, seg = idx & 3;
            *(float4*)(As + row * 40 + seg * 8) =
                *(const float4*)(A + (size_t)(m0 + row) * 256 + kc + seg * 8);
            *(float4*)(Bs + row * 40 + seg * 8) =
                *(const float4*)(B + (size_t)row * 256 + kc + seg * 8);
        }
        __syncthreads();
        #pragma unroll
        for (int k16 = 0; k16 < 2; k16++) {
            unsigned af[2][4];
            #pragma unroll
            for (int mi = 0; mi < 2; mi++) {
                int r = wm * 32 + mi * 16 + g;
                af[mi][0] = *(unsigned*)&As[r * 40 + k16*16 + t4*2];
                af[mi][1] = *(unsigned*)&As[(r + 8) * 40 + k16*16 + t4*2];
                af[mi][2] = *(unsigned*)&As[r * 40 + k16*16 + 8 + t4*2];
                af[mi][3] = *(unsigned*)&As[(r + 8) * 40 + k16*16 + 8 + t4*2];
            }
            #pragma unroll
            for (int ni = 0; ni < 8; ni++) {
                int cc = wn * 64 + ni * 8 + g;
                unsigned b0 = *(unsigned*)&Bs[cc * 40 + k16*16 + t4*2];
                unsigned b1 = *(unsigned*)&Bs[cc * 40 + k16*16 + 8 + t4*2];
                mma_f16(acc[0][ni], af[0], b0, b1);
                mma_f16(acc[1][ni], af[1], b0, b1);
            }
        }
        __syncthreads();
    }
}

// qkv: q,k -> fp16 (k scaled u/16); v -> bf16 token-pair packed
__global__ __launch_bounds__(256, 2)
void gemm_qkv(const float* __restrict__ bq, const float* __restrict__ bk,
              const float* __restrict__ bv) {
    const int n0 = blockIdx.x * 128, m0 = blockIdx.y * 128;
    const float* Bi = (n0 < 256) ? bq : (n0 < 512) ? bk : bv;
    __shared__ __align__(16) __half As[128 * 40];
    __shared__ __align__(16) __half Bs[128 * 40];
    float acc[2][8][4];
    gemm_core_h(g_th, g_wh + (size_t)n0 * 256, m0, As, Bs, acc);
    const int lane = threadIdx.x & 31, warp = threadIdx.x >> 5;
    const int wm = warp >> 1, wn = warp & 1, g = lane >> 2, t4 = lane & 3;
    #pragma unroll
    for (int mi = 0; mi < 2; mi++) {
        int rbase = m0 + wm * 32 + mi * 16 + g;
        #pragma unroll
        for (int ni = 0; ni < 8; ni++) {
            int cl = wn * 64 + ni * 8 + t4 * 2, cg = n0 + cl;
            #pragma unroll
            for (int half = 0; half < 2; half++) {
                int rr = rbase + half * 8;
                float v0 = acc[mi][ni][half * 2 + 0] + Bi[(n0 & 255) + cl];
                float v1 = acc[mi][ni][half * 2 + 1] + Bi[(n0 & 255) + cl + 1];
                if (cg < 512) {
                    if (cg >= 256) { float us = g_u[rr] * 0.0625f; v0 *= us; v1 *= us; }
                    *(__half2*)&g_qkh[(size_t)rr * 512 + cg] = __floats2half2_rn(v0, v1);
                } else {
                    int c2 = cg - 512, t2 = rr >> 1, par = rr & 1;
                    __nv_bfloat16* vb = (__nv_bfloat16*)g_vp;
                    vb[((size_t)t2 * 256 + c2) * 2 + par]     = __float2bfloat16(v0);
                    vb[((size_t)t2 * 256 + c2 + 1) * 2 + par] = __float2bfloat16(v1);
                }
            }
        }
    }
}

// proj transposed: out[b][c][s] = x + Wp @ O^T + bp
__global__ __launch_bounds__(256, 2)
void gemm_proj_t(const float* __restrict__ x, const float* __restrict__ bias,
                 float* __restrict__ out) {
    const int n0 = blockIdx.x * 128;
    const int m0 = blockIdx.y * 128;
    __shared__ __align__(16) __half As[128 * 40];
    __shared__ __align__(16) __half Bs[128 * 40];
    float acc[2][8][4];
    gemm_core_h(g_wh + (size_t)768 * 256, g_oh + (size_t)n0 * 256, m0, As, Bs, acc);
    const int lane = threadIdx.x & 31, warp = threadIdx.x >> 5;
    const int wm = warp >> 1, wn = warp & 1, g = lane >> 2, t4 = lane & 3;
    #pragma unroll
    for (int mi = 0; mi < 2; mi++) {
        int chb = m0 + wm * 32 + mi * 16 + g;
        #pragma unroll
        for (int ni = 0; ni < 8; ni++) {
            int tok = n0 + wn * 64 + ni * 8 + t4 * 2;
            int bb = tok >> 12, s = tok & 4095;
            #pragma unroll
            for (int half = 0; half < 2; half++) {
                int ch = chb + half * 8;
                size_t idx = ((size_t)(bb * CCH + ch)) * BHW + s;
                float2 xv = *(const float2*)(x + idx);
                *(float2*)(out + idx) =
                    make_float2(acc[mi][ni][half * 2 + 0] + bias[ch] + xv.x,
                                acc[mi][ni][half * 2 + 1] + bias[ch] + xv.y);
            }
        }
    }
}

// ---------------- u = sigmoid(t @ wu^T + bu) ---------------------------------
__global__ void u_kernel(const float* __restrict__ wu, const float* __restrict__ bu,
                         float* __restrict__ dout_u) {
    int i = blockIdx.x * 8 + (threadIdx.x >> 5);
    int lane = threadIdx.x & 31;
    const __half2* t2 = (const __half2*)(g_th + (size_t)i * CCH);
    float s = 0.f;
    #pragma unroll
    for (int j = 0; j < 4; j++) {
        float2 f = __half22float2(t2[lane + j * 32]);
        int c = (lane + j * 32) * 2;
        s += f.x * wu[c] + f.y * wu[c + 1];
    }
    #pragma unroll
    for (int o = 16; o; o >>= 1) s += __shfl_down_sync(~0u, s, o);
    if (lane == 0) {
        float uu = 1.f / (1.f + expf(-(s + bu[0])));
        g_u[i] = uu; dout_u[i] = uu;
    }
}

// ---------------- FA2-style flash: 2 CTAs/SM, S in registers -----------------
__global__ __launch_bounds__(256, 2)
void flash5(float* __restrict__ unused) {
    extern __shared__ __align__(16) char dsmb[];
    float* dsm = (float*)dsmb;
    uint32_t sb = smem_u32(dsmb);
    int b = blockIdx.y, q0 = blockIdx.x * 64;
    int tid = threadIdx.x, lane = tid & 31, warp = tid >> 5;
    int g = lane >> 2, t4 = lane & 3;
    int wm = warp >> 1, wn = warp & 1;
    size_t tokb = (size_t)b * BHW;
    const __half* Qg = g_qkh + (tokb + q0) * 512;
    const __half* Kg = g_qkh + tokb * 512 + 256;
    const unsigned* Vg = g_vp + (size_t)b * 2048 * 256;

    for (int i = tid; i < 2048; i += 256) {          // Q [64][264h]
        int r = i >> 5, c8 = i & 31;
        cp16(sb + QB + r * 528 + c8 * 16, Qg + (size_t)r * 512 + c8 * 8);
    }
    for (int i = tid; i < 1024; i += 256) {          // K(0)
        int r = i >> 5, c8 = i & 31;
        cp16(sb + KB(0) + r * 528 + c8 * 16, Kg + (size_t)r * 512 + c8 * 8);
    }
    for (int i = tid; i < 1024; i += 256) {          // V(0)
        int r = i >> 6, c4 = (i & 63) * 4;
        cp16(sb + VB(0) + r * 1056 + c4 * 4, Vg + (size_t)r * 256 + c4);
    }
    CP_COMMIT;

    // ldmatrix addresses: A (Q) and B (K) lane mappings
    const uint32_t qa = sb + QB +
        ((wm * 16 + (lane & 7) + ((lane >> 3) & 1) * 8) * 264 + ((lane >> 4) & 1) * 8) * 2;
    const int klrow = ((lane >> 4) & 1) * 8 + (lane & 7);
    const int klkof = ((lane >> 3) & 1) * 8;

    float acc[16][4];
    #pragma unroll
    for (int ni = 0; ni < 16; ni++)
        #pragma unroll
        for (int e = 0; e < 4; e++) acc[ni][e] = 0.f;
    float lac0 = 0.f, lac1 = 0.f;

    for (int it = 0; it < FITERS; ++it) {
        CP_WAIT0; __syncthreads();
        if (it + 1 < FITERS) {
            const __half* kn = Kg + (size_t)(it + 1) * 32 * 512;
            const unsigned* vn = Vg + (size_t)(it + 1) * 16 * 256;
            uint32_t kd = sb + KB((it + 1) & 1), vd = sb + VB((it + 1) & 1);
            for (int i = tid; i < 1024; i += 256) {
                int r = i >> 5, c8 = i & 31;
                cp16(kd + r * 528 + c8 * 16, kn + (size_t)r * 512 + c8 * 8);
            }
            for (int i = tid; i < 1024; i += 256) {
                int r = i >> 6, c4 = (i & 63) * 4;
                cp16(vd + r * 1056 + c4 * 4, vn + (size_t)r * 256 + c4);
            }
            CP_COMMIT;
        }
        // QK: S for rows wm*16..+16 x all 32 keys (sacc[ngroup][4])
        uint32_t kbase = sb + KB(it & 1) + (klrow * 264 + klkof) * 2;
        float sacc[4][4];
        #pragma unroll
        for (int ni = 0; ni < 4; ni++)
            #pragma unroll
            for (int e = 0; e < 4; e++) sacc[ni][e] = 0.f;
        #pragma unroll
        for (int k16 = 0; k16 < 16; k16++) {
            unsigned a0, a1, a2, a3;
            ldm4(a0, a1, a2, a3, qa + k16 * 32);
            unsigned af[4] = { a0, a1, a2, a3 };
            #pragma unroll
            for (int p = 0; p < 2; p++) {
                unsigned m0, m1, m2, m3;
                ldm4(m0, m1, m2, m3, kbase + p * 8448 + k16 * 32);
                mma_f16(sacc[p*2],     af, m0, m1);
                mma_f16(sacc[p*2 + 1], af, m2, m3);
            }
        }
        // exp + repack S->P fragments (registers only)
        unsigned af2[2][4];
        #pragma unroll
        for (int pp = 0; pp < 2; pp++) {
            float e00 = __expf(sacc[pp*2][0]),   e01 = __expf(sacc[pp*2][1]);
            float e02 = __expf(sacc[pp*2][2]),   e03 = __expf(sacc[pp*2][3]);
            float e10 = __expf(sacc[pp*2+1][0]), e11 = __expf(sacc[pp*2+1][1]);
            float e12 = __expf(sacc[pp*2+1][2]), e13 = __expf(sacc[pp*2+1][3]);
            if (wn == 0) { lac0 += e00 + e01 + e10 + e11; lac1 += e02 + e03 + e12 + e13; }
            af2[pp][0] = pack_bf(e00, e01);
            af2[pp][1] = pack_bf(e02, e03);
            af2[pp][2] = pack_bf(e10, e11);
            af2[pp][3] = pack_bf(e12, e13);
        }
        // PV: O rows wm*16 x cols wn*128
        const unsigned* V = (const unsigned*)(dsmb + VB(it & 1));
        #pragma unroll
        for (int k16 = 0; k16 < 2; k16++) {
            #pragma unroll
            for (int ni = 0; ni < 16; ni++) {
                int c = wn * 128 + ni * 8 + g;
                unsigned b0 = V[(k16*8 + t4) * 264 + c];
                unsigned b1 = V[(k16*8 + 4 + t4) * 264 + c];
                mma_bf16(acc[ni], af2[k16], b0, b1);
            }
        }
    }

    if (wn == 0) {
        lac0 += __shfl_xor_sync(~0u, lac0, 1);
        lac0 += __shfl_xor_sync(~0u, lac0, 2);
        lac1 += __shfl_xor_sync(~0u, lac1, 1);
        lac1 += __shfl_xor_sync(~0u, lac1, 2);
        if (t4 == 0) {
            dsm[SLB/4 + wm*16 + g]     = lac0;
            dsm[SLB/4 + wm*16 + g + 8] = lac1;
        }
    }
    __syncthreads();
    {
        int r = wm * 16 + g;
        float i0 = 1.f / dsm[SLB/4 + r];
        float i1 = 1.f / dsm[SLB/4 + r + 8];
        __half* o0 = g_oh + (tokb + q0 + r) * 256;
        __half* o1 = g_oh + (tokb + q0 + r + 8) * 256;
        #pragma unroll
        for (int ni = 0; ni < 16; ni++) {
            int cc = wn * 128 + ni * 8 + t4 * 2;
            *(__half2*)&o0[cc] = __floats2half2_rn(acc[ni][0] * i0, acc[ni][1] * i0);
            *(__half2*)&o1[cc] = __floats2half2_rn(acc[ni][2] * i1, acc[ni][3] * i1);
        }
    }
    (void)unused;
}

// ---------------- launch -----------------------------------------------------
extern "C" void kernel_launch(void* const* d_in, const int* in_sizes, int n_in,
                              void* d_out, int out_size) {
    (void)in_sizes; (void)n_in; (void)out_size;
    const float* x     = (const float*)d_in[0];
    const float* gamma = (const float*)d_in[1];
    const float* beta  = (const float*)d_in[2];
    const float* wq = (const float*)d_in[3],  *bq = (const float*)d_in[4];
    const float* wk = (const float*)d_in[5],  *bk = (const float*)d_in[6];
    const float* wv = (const float*)d_in[7],  *bv = (const float*)d_in[8];
    const float* wu = (const float*)d_in[9],  *bu = (const float*)d_in[10];
    const float* wp = (const float*)d_in[11], *bp = (const float*)d_in[12];
    float* out = (float*)d_out;

    cudaFuncSetAttribute(flash5, cudaFuncAttributeMaxDynamicSharedMemorySize, FSMEM);

    gn_stats<<<NBAT * NGRP, 256>>>(x);
    gn_apply<<<dim3(BHW / 32, CCH / 32, NBAT), dim3(32, 8)>>>(x, gamma, beta);
    u_kernel<<<NTOK / 8, 256>>>(wu, bu, out + OUT_MAIN);
    w_pack<<<1024, 256>>>(wq, wk, wv, wp);
    gemm_qkv<<<dim3(6, 128), 256>>>(bq, bk, bv);
    flash5<<<dim3(BHW / 64, NBAT), 256, FSMEM>>>(out);
    gemm_proj_t<<<dim3(128, 2), 256>>>(x, bp, out);
}

// round 14
// speedup vs baseline: 1.2204x; 1.2204x over previous
#include <cuda_runtime.h>
#include <cuda_bf16.h>
#include <cuda_fp16.h>
#include <stdint.h>

#define BHW   4096
#define CCH   256
#define NBAT  4
#define NTOK  16384
#define NGRP  32
#define GELEMS (8*BHW)
#define OUT_MAIN ((size_t)NBAT*CCH*BHW)

#define FITERS 128
// flash smem BYTE offsets
#define KB(i)  ((i)*16896)              /* K fp16 [32][264] x2  */
#define VB(j)  (33792 + (j)*16896)      /* V u32 [16][264] x3   */
#define PB(p)  (84480 + (p)*5120)       /* P u32 [64][20] x2    */
#define SLB    94720                    /* l[64] fp32           */
#define QSTGB  33792                    /* Q staging [64][264h], overlaps V0/V1 */
#define FSMEM  94976

__device__ __half   g_th[(size_t)NTOK*CCH];
__device__ __half   g_qkh[(size_t)NTOK*512];
__device__ unsigned g_vp[(size_t)(NTOK/2)*256];
__device__ __half   g_oh[(size_t)NTOK*CCH];
__device__ __half   g_wh[(size_t)1024*256];
__device__ float    g_u[NTOK];
__device__ float    g_mu[NBAT*NGRP];
__device__ float    g_rs[NBAT*NGRP];

__device__ __forceinline__ unsigned fu(float f) { return __float_as_uint(f); }
__device__ __forceinline__ void mma_f16(float* c, const unsigned* a, unsigned b0, unsigned b1) {
    asm volatile("mma.sync.aligned.m16n8k16.row.col.f32.f16.f16.f32 "
                 "{%0,%1,%2,%3}, {%4,%5,%6,%7}, {%8,%9}, {%0,%1,%2,%3};"
                 : "+f"(c[0]), "+f"(c[1]), "+f"(c[2]), "+f"(c[3])
                 : "r"(a[0]), "r"(a[1]), "r"(a[2]), "r"(a[3]), "r"(b0), "r"(b1));
}
__device__ __forceinline__ void mma_bf16(float* c, const unsigned* a, unsigned b0, unsigned b1) {
    asm volatile("mma.sync.aligned.m16n8k16.row.col.f32.bf16.bf16.f32 "
                 "{%0,%1,%2,%3}, {%4,%5,%6,%7}, {%8,%9}, {%0,%1,%2,%3};"
                 : "+f"(c[0]), "+f"(c[1]), "+f"(c[2]), "+f"(c[3])
                 : "r"(a[0]), "r"(a[1]), "r"(a[2]), "r"(a[3]), "r"(b0), "r"(b1));
}
__device__ __forceinline__ uint32_t smem_u32(const void* p) {
    uint32_t a;
    asm("{ .reg .u64 t; cvta.to.shared.u64 t, %1; cvt.u32.u64 %0, t; }" : "=r"(a) : "l"(p));
    return a;
}
__device__ __forceinline__ void cp16(uint32_t saddr, const void* g) {
    asm volatile("cp.async.cg.shared.global [%0], [%1], 16;" :: "r"(saddr), "l"(g));
}
#define CP_COMMIT asm volatile("cp.async.commit_group;" ::: "memory")
#define CP_WAIT0  asm volatile("cp.async.wait_group 0;" ::: "memory")
__device__ __forceinline__ unsigned pack_bf(float lo, float hi) {
    unsigned r;
    asm("cvt.rn.bf16x2.f32 %0, %1, %2;" : "=r"(r) : "f"(hi), "f"(lo));
    return r;
}

// ---------------- GroupNorm --------------------------------------------------
__global__ void gn_stats(const float* __restrict__ x) {
    int bg = blockIdx.x;
    const float4* p = (const float4*)(x + (size_t)bg * GELEMS);
    float s = 0.f, ss = 0.f;
    for (int i = threadIdx.x; i < GELEMS/4; i += blockDim.x) {
        float4 v = p[i];
        s += v.x + v.y + v.z + v.w;
        ss += v.x*v.x + v.y*v.y + v.z*v.z + v.w*v.w;
    }
    __shared__ float rs[8], rss[8];
    #pragma unroll
    for (int o = 16; o; o >>= 1) { s += __shfl_down_sync(~0u, s, o); ss += __shfl_down_sync(~0u, ss, o); }
    if ((threadIdx.x & 31) == 0) { rs[threadIdx.x >> 5] = s; rss[threadIdx.x >> 5] = ss; }
    __syncthreads();
    if (threadIdx.x < 32) {
        s  = (threadIdx.x < 8) ? rs[threadIdx.x]  : 0.f;
        ss = (threadIdx.x < 8) ? rss[threadIdx.x] : 0.f;
        #pragma unroll
        for (int o = 4; o; o >>= 1) { s += __shfl_down_sync(~0u, s, o); ss += __shfl_down_sync(~0u, ss, o); }
        if (threadIdx.x == 0) {
            float mu = s / (float)GELEMS;
            float var = ss / (float)GELEMS - mu * mu;
            g_mu[bg] = mu; g_rs[bg] = rsqrtf(var + 1e-6f);
        }
    }
}

__global__ void gn_apply(const float* __restrict__ x, const float* __restrict__ gamma,
                         const float* __restrict__ beta) {
    __shared__ float tile[32][33];
    int b = blockIdx.z, c0 = blockIdx.y * 32, s0 = blockIdx.x * 32;
    int tx = threadIdx.x, ty = threadIdx.y;
    for (int i = ty; i < 32; i += 8) {
        int c = c0 + i, bg = b * NGRP + (c >> 3);
        float v = x[((size_t)(b * CCH + c)) * BHW + s0 + tx];
        tile[i][tx] = (v - g_mu[bg]) * g_rs[bg] * gamma[c] + beta[c];
    }
    __syncthreads();
    for (int i = ty; i < 32; i += 8)
        g_th[((size_t)(b * BHW + s0 + i)) * CCH + c0 + tx] = __float2half(tile[tx][i]);
}

// ---------------- weight pack ------------------------------------------------
__global__ void w_pack(const float* __restrict__ wq, const float* __restrict__ wk,
                       const float* __restrict__ wv, const float* __restrict__ wp) {
    int r = blockIdx.x, tid = threadIdx.x;
    const float* w = (r < 256) ? wq : (r < 512) ? wk : (r < 768) ? wv : wp;
    g_wh[(size_t)r * 256 + tid] = __float2half(w[(size_t)(r & 255) * 256 + tid]);
}

// ---------------- fp16 gemm core (K=256) -------------------------------------
__device__ __forceinline__ void gemm_core_h(const __half* A, const __half* B, int m0,
                                            __half* As, __half* Bs, float acc[2][8][4]) {
    const int tid = threadIdx.x, lane = tid & 31, warp = tid >> 5;
    const int wm = warp >> 1, wn = warp & 1, g = lane >> 2, t4 = lane & 3;
    #pragma unroll
    for (int mi = 0; mi < 2; mi++)
        #pragma unroll
        for (int ni = 0; ni < 8; ni++)
            #pragma unroll
            for (int e = 0; e < 4; e++) acc[mi][ni][e] = 0.f;
    for (int kc = 0; kc < 256; kc += 32) {
        #pragma unroll
        for (int it = 0; it < 2; it++) {
            int idx = tid + it * 256, row = idx >> 2, seg = idx & 3;
            *(float4*)(As + row * 40 + seg * 8) =
                *(const float4*)(A + (size_t)(m0 + row) * 256 + kc + seg * 8);
            *(float4*)(Bs + row * 40 + seg * 8) =
                *(const float4*)(B + (size_t)row * 256 + kc + seg * 8);
        }
        __syncthreads();
        #pragma unroll
        for (int k16 = 0; k16 < 2; k16++) {
            unsigned af[2][4];
            #pragma unroll
            for (int mi = 0; mi < 2; mi++) {
                int r = wm * 32 + mi * 16 + g;
                af[mi][0] = *(unsigned*)&As[r * 40 + k16*16 + t4*2];
                af[mi][1] = *(unsigned*)&As[(r + 8) * 40 + k16*16 + t4*2];
                af[mi][2] = *(unsigned*)&As[r * 40 + k16*16 + 8 + t4*2];
                af[mi][3] = *(unsigned*)&As[(r + 8) * 40 + k16*16 + 8 + t4*2];
            }
            #pragma unroll
            for (int ni = 0; ni < 8; ni++) {
                int cc = wn * 64 + ni * 8 + g;
                unsigned b0 = *(unsigned*)&Bs[cc * 40 + k16*16 + t4*2];
                unsigned b1 = *(unsigned*)&Bs[cc * 40 + k16*16 + 8 + t4*2];
                mma_f16(acc[0][ni], af[0], b0, b1);
                mma_f16(acc[1][ni], af[1], b0, b1);
            }
        }
        __syncthreads();
    }
}

// qkv: q,k -> fp16 (k scaled u/16); v -> bf16 token-pair packed
__global__ __launch_bounds__(256, 2)
void gemm_qkv(const float* __restrict__ bq, const float* __restrict__ bk,
              const float* __restrict__ bv) {
    const int n0 = blockIdx.x * 128, m0 = blockIdx.y * 128;
    const float* Bi = (n0 < 256) ? bq : (n0 < 512) ? bk : bv;
    __shared__ __align__(16) __half As[128 * 40];
    __shared__ __align__(16) __half Bs[128 * 40];
    float acc[2][8][4];
    gemm_core_h(g_th, g_wh + (size_t)n0 * 256, m0, As, Bs, acc);
    const int lane = threadIdx.x & 31, warp = threadIdx.x >> 5;
    const int wm = warp >> 1, wn = warp & 1, g = lane >> 2, t4 = lane & 3;
    #pragma unroll
    for (int mi = 0; mi < 2; mi++) {
        int rbase = m0 + wm * 32 + mi * 16 + g;
        #pragma unroll
        for (int ni = 0; ni < 8; ni++) {
            int cl = wn * 64 + ni * 8 + t4 * 2, cg = n0 + cl;
            #pragma unroll
            for (int half = 0; half < 2; half++) {
                int rr = rbase + half * 8;
                float v0 = acc[mi][ni][half * 2 + 0] + Bi[(n0 & 255) + cl];
                float v1 = acc[mi][ni][half * 2 + 1] + Bi[(n0 & 255) + cl + 1];
                if (cg < 512) {
                    if (cg >= 256) { float us = g_u[rr] * 0.0625f; v0 *= us; v1 *= us; }
                    *(__half2*)&g_qkh[(size_t)rr * 512 + cg] = __floats2half2_rn(v0, v1);
                } else {
                    int c2 = cg - 512, t2 = rr >> 1, par = rr & 1;
                    __nv_bfloat16* vb = (__nv_bfloat16*)g_vp;
                    vb[((size_t)t2 * 256 + c2) * 2 + par]     = __float2bfloat16(v0);
                    vb[((size_t)t2 * 256 + c2 + 1) * 2 + par] = __float2bfloat16(v1);
                }
            }
        }
    }
}

// proj transposed: out[b][c][s] = x + Wp @ O^T + bp
__global__ __launch_bounds__(256, 2)
void gemm_proj_t(const float* __restrict__ x, const float* __restrict__ bias,
                 float* __restrict__ out) {
    const int n0 = blockIdx.x * 128;
    const int m0 = blockIdx.y * 128;
    __shared__ __align__(16) __half As[128 * 40];
    __shared__ __align__(16) __half Bs[128 * 40];
    float acc[2][8][4];
    gemm_core_h(g_wh + (size_t)768 * 256, g_oh + (size_t)n0 * 256, m0, As, Bs, acc);
    const int lane = threadIdx.x & 31, warp = threadIdx.x >> 5;
    const int wm = warp >> 1, wn = warp & 1, g = lane >> 2, t4 = lane & 3;
    #pragma unroll
    for (int mi = 0; mi < 2; mi++) {
        int chb = m0 + wm * 32 + mi * 16 + g;
        #pragma unroll
        for (int ni = 0; ni < 8; ni++) {
            int tok = n0 + wn * 64 + ni * 8 + t4 * 2;
            int bb = tok >> 12, s = tok & 4095;
            #pragma unroll
            for (int half = 0; half < 2; half++) {
                int ch = chb + half * 8;
                size_t idx = ((size_t)(bb * CCH + ch)) * BHW + s;
                float2 xv = *(const float2*)(x + idx);
                *(float2*)(out + idx) =
                    make_float2(acc[mi][ni][half * 2 + 0] + bias[ch] + xv.x,
                                acc[mi][ni][half * 2 + 1] + bias[ch] + xv.y);
            }
        }
    }
}

// ---------------- u = sigmoid(t @ wu^T + bu) ---------------------------------
__global__ void u_kernel(const float* __restrict__ wu, const float* __restrict__ bu,
                         float* __restrict__ dout_u) {
    int i = blockIdx.x * 8 + (threadIdx.x >> 5);
    int lane = threadIdx.x & 31;
    const __half2* t2 = (const __half2*)(g_th + (size_t)i * CCH);
    float s = 0.f;
    #pragma unroll
    for (int j = 0; j < 4; j++) {
        float2 f = __half22float2(t2[lane + j * 32]);
        int c = (lane + j * 32) * 2;
        s += f.x * wu[c] + f.y * wu[c + 1];
    }
    #pragma unroll
    for (int o = 16; o; o >>= 1) s += __shfl_down_sync(~0u, s, o);
    if (lane == 0) {
        float uu = 1.f / (1.f + expf(-(s + bu[0])));
        g_u[i] = uu; dout_u[i] = uu;
    }
}

// -------- flash6: 16 warps = 4 QK + 8 PV + 4 loaders, P via smem frags -------
__global__ __launch_bounds__(512, 1)
void flash6(float* __restrict__ unused) {
    extern __shared__ __align__(16) char dsmb[];
    float* dsm = (float*)dsmb;
    uint32_t sb = smem_u32(dsmb);
    int b = blockIdx.y, q0 = blockIdx.x * 64;
    int tid = threadIdx.x, lane = tid & 31, warp = tid >> 5;
    int g = lane >> 2, t4 = lane & 3;
    size_t tokb = (size_t)b * BHW;
    const __half* Qg = g_qkh + (tokb + q0) * 512;
    const __half* Kg = g_qkh + tokb * 512 + 256;
    const unsigned* Vg = g_vp + (size_t)b * 2048 * 256;

    // stage Q, read frags, release area
    for (int i = tid; i < 2048; i += 512) {
        int r = i >> 5, c8 = i & 31;
        cp16(sb + QSTGB + r * 528 + c8 * 16, Qg + (size_t)r * 512 + c8 * 8);
    }
    CP_COMMIT; CP_WAIT0; __syncthreads();

    float rp[64];   // QK warps: Q frags (bit-cast). PV warps: O accumulator.
    if (warp < 4) {
        int r0 = warp * 16 + g;
        const __half* q = (const __half*)(dsmb + QSTGB);
        #pragma unroll
        for (int k16 = 0; k16 < 16; k16++) {
            rp[k16*4+0] = __uint_as_float(*(const unsigned*)&q[r0 * 264 + k16*16 + t4*2]);
            rp[k16*4+1] = __uint_as_float(*(const unsigned*)&q[(r0+8) * 264 + k16*16 + t4*2]);
            rp[k16*4+2] = __uint_as_float(*(const unsigned*)&q[r0 * 264 + k16*16 + 8 + t4*2]);
            rp[k16*4+3] = __uint_as_float(*(const unsigned*)&q[(r0+8) * 264 + k16*16 + 8 + t4*2]);
        }
    } else {
        #pragma unroll
        for (int j = 0; j < 64; j++) rp[j] = 0.f;
    }
    __syncthreads();

    for (int i = tid; i < 1024; i += 512) {          // K(0)
        int r = i >> 5, c8 = i & 31;
        cp16(sb + KB(0) + r * 528 + c8 * 16, Kg + (size_t)r * 512 + c8 * 8);
    }
    for (int i = tid; i < 1024; i += 512) {          // V(0)
        int r = i >> 6, c4 = (i & 63) * 4;
        cp16(sb + VB(0) + r * 1056 + c4 * 4, Vg + (size_t)r * 256 + c4);
    }
    CP_COMMIT;

    int pw = warp - 4, wm = pw & 3, wn = pw >> 2;    // PV decomposition
    float lac0 = 0.f, lac1 = 0.f;

    for (int it = 0; it <= FITERS; ++it) {
        CP_WAIT0; __syncthreads();
        if (warp >= 12) {                            // loaders
            if (it + 1 < FITERS) {
                int t2 = tid - 384;
                const __half* kn = Kg + (size_t)(it + 1) * 32 * 512;
                const unsigned* vn = Vg + (size_t)(it + 1) * 16 * 256;
                uint32_t kd = sb + KB((it + 1) & 1), vd = sb + VB((it + 1) % 3);
                for (int i = t2; i < 1024; i += 128) {
                    int r = i >> 5, c8 = i & 31;
                    cp16(kd + r * 528 + c8 * 16, kn + (size_t)r * 512 + c8 * 8);
                }
                for (int i = t2; i < 1024; i += 128) {
                    int r = i >> 6, c4 = (i & 63) * 4;
                    cp16(vd + r * 1056 + c4 * 4, vn + (size_t)r * 256 + c4);
                }
                CP_COMMIT;
            }
        } else if (warp < 4) {                       // QK + exp + P pack
            if (it < FITERS) {
                const __half* kb = (const __half*)(dsmb + KB(it & 1));
                float sacc[4][4];
                #pragma unroll
                for (int ni = 0; ni < 4; ni++)
                    #pragma unroll
                    for (int e = 0; e < 4; e++) sacc[ni][e] = 0.f;
                #pragma unroll
                for (int k16 = 0; k16 < 16; k16++) {
                    unsigned af[4] = { fu(rp[k16*4]), fu(rp[k16*4+1]), fu(rp[k16*4+2]), fu(rp[k16*4+3]) };
                    #pragma unroll
                    for (int ni = 0; ni < 4; ni++) {
                        int c = ni * 8 + g;
                        unsigned b0 = *(const unsigned*)&kb[c * 264 + k16*16 + t4*2];
                        unsigned b1 = *(const unsigned*)&kb[c * 264 + k16*16 + 8 + t4*2];
                        mma_f16(sacc[ni], af, b0, b1);
                    }
                }
                unsigned* P = (unsigned*)(dsmb + PB(it & 1));
                int r0 = warp * 16 + g;
                #pragma unroll
                for (int ni = 0; ni < 4; ni++) {
                    float e0 = __expf(sacc[ni][0]), e1 = __expf(sacc[ni][1]);
                    float e2 = __expf(sacc[ni][2]), e3 = __expf(sacc[ni][3]);
                    lac0 += e0 + e1; lac1 += e2 + e3;
                    P[r0 * 20 + ni*4 + t4]       = pack_bf(e0, e1);
                    P[(r0 + 8) * 20 + ni*4 + t4] = pack_bf(e2, e3);
                }
            }
        } else {                                     // PV (8 warps)
            if (it >= 1) {
                int pit = it - 1;
                const unsigned* P = (const unsigned*)(dsmb + PB(pit & 1));
                const unsigned* V = (const unsigned*)(dsmb + VB(pit % 3));
                int m0 = wm * 16;
                #pragma unroll
                for (int k16 = 0; k16 < 2; k16++) {
                    unsigned a[4] = {
                        P[(m0 + g) * 20 + k16*8 + t4],
                        P[(m0 + 8 + g) * 20 + k16*8 + t4],
                        P[(m0 + g) * 20 + k16*8 + 4 + t4],
                        P[(m0 + 8 + g) * 20 + k16*8 + 4 + t4] };
                    #pragma unroll
                    for (int ni = 0; ni < 16; ni++) {
                        int c = wn * 128 + ni * 8 + g;
                        unsigned b0 = V[(k16*8 + t4) * 264 + c];
                        unsigned b1 = V[(k16*8 + 4 + t4) * 264 + c];
                        mma_bf16(&rp[ni*4], a, b0, b1);
                    }
                }
            }
        }
    }

    if (warp < 4) {                                  // l reduce (QK warps)
        lac0 += __shfl_xor_sync(~0u, lac0, 1);
        lac0 += __shfl_xor_sync(~0u, lac0, 2);
        lac1 += __shfl_xor_sync(~0u, lac1, 1);
        lac1 += __shfl_xor_sync(~0u, lac1, 2);
        if (t4 == 0) {
            dsm[SLB/4 + warp*16 + g]     = lac0;
            dsm[SLB/4 + warp*16 + g + 8] = lac1;
        }
    }
    __syncthreads();
    if (warp >= 4 && warp < 12) {                    // epilogue (PV warps)
        int r = wm * 16 + g;
        float i0 = 1.f / dsm[SLB/4 + r];
        float i1 = 1.f / dsm[SLB/4 + r + 8];
        __half* o0 = g_oh + (tokb + q0 + r) * 256;
        __half* o1 = g_oh + (tokb + q0 + r + 8) * 256;
        #pragma unroll
        for (int ni = 0; ni < 16; ni++) {
            int cc = wn * 128 + ni * 8 + t4 * 2;
            *(__half2*)&o0[cc] = __floats2half2_rn(rp[ni*4] * i0,   rp[ni*4+1] * i0);
            *(__half2*)&o1[cc] = __floats2half2_rn(rp[ni*4+2] * i1, rp[ni*4+3] * i1);
        }
    }
    (void)unused;
}

// ---------------- launch -----------------------------------------------------
extern "C" void kernel_launch(void* const* d_in, const int* in_sizes, int n_in,
                              void* d_out, int out_size) {
    (void)in_sizes; (void)n_in; (void)out_size;
    const float* x     = (const float*)d_in[0];
    const float* gamma = (const float*)d_in[1];
    const float* beta  = (const float*)d_in[2];
    const float* wq = (const float*)d_in[3],  *bq = (const float*)d_in[4];
    const float* wk = (const float*)d_in[5],  *bk = (const float*)d_in[6];
    const float* wv = (const float*)d_in[7],  *bv = (const float*)d_in[8];
    const float* wu = (const float*)d_in[9],  *bu = (const float*)d_in[10];
    const float* wp = (const float*)d_in[11], *bp = (const float*)d_in[12];
    float* out = (float*)d_out;

    cudaFuncSetAttribute(flash6, cudaFuncAttributeMaxDynamicSharedMemorySize, FSMEM);

    gn_stats<<<NBAT * NGRP, 256>>>(x);
    gn_apply<<<dim3(BHW / 32, CCH / 32, NBAT), dim3(32, 8)>>>(x, gamma, beta);
    u_kernel<<<NTOK / 8, 256>>>(wu, bu, out + OUT_MAIN);
    w_pack<<<1024, 256>>>(wq, wk, wv, wp);
    gemm_qkv<<<dim3(6, 128), 256>>>(bq, bk, bv);
    flash6<<<dim3(BHW / 64, NBAT), 512, FSMEM>>>(out);
    gemm_proj_t<<<dim3(128, 2), 256>>>(x, bp, out);
}

// round 15
// speedup vs baseline: 1.2667x; 1.0379x over previous
#include <cuda_runtime.h>
#include <cuda_bf16.h>
#include <cuda_fp16.h>
#include <stdint.h>

#define BHW   4096
#define CCH   256
#define NBAT  4
#define NTOK  16384
#define NGRP  32
#define GELEMS (8*BHW)
#define OUT_MAIN ((size_t)NBAT*CCH*BHW)

#define FITERS 64
// flash smem BYTE offsets (BN=64)
#define KB(i)  ((i)*33792)              /* K fp16 [64][264] x2  */
#define VB(j)  (67584 + (j)*33792)      /* V u32 [32][264] x3   */
#define PB(p)  (169344 + (p)*10240)     /* P u32 [64][40] x2    */
#define SLB    189824                   /* l[64] fp32           */
#define QSTGB  67584                    /* Q staging overlaps V0 */
#define FSMEM  190080

__device__ __half   g_th[(size_t)NTOK*CCH];
__device__ __half   g_qkh[(size_t)NTOK*512];
__device__ unsigned g_vp[(size_t)(NTOK/2)*256];
__device__ __half   g_oh[(size_t)NTOK*CCH];
__device__ __half   g_wh[(size_t)1024*256];
__device__ float    g_u[NTOK];
__device__ float    g_mu[NBAT*NGRP];
__device__ float    g_rs[NBAT*NGRP];

__device__ __forceinline__ unsigned fu(float f) { return __float_as_uint(f); }
__device__ __forceinline__ void mma_f16(float* c, const unsigned* a, unsigned b0, unsigned b1) {
    asm volatile("mma.sync.aligned.m16n8k16.row.col.f32.f16.f16.f32 "
                 "{%0,%1,%2,%3}, {%4,%5,%6,%7}, {%8,%9}, {%0,%1,%2,%3};"
                 : "+f"(c[0]), "+f"(c[1]), "+f"(c[2]), "+f"(c[3])
                 : "r"(a[0]), "r"(a[1]), "r"(a[2]), "r"(a[3]), "r"(b0), "r"(b1));
}
__device__ __forceinline__ void mma_bf16(float* c, const unsigned* a, unsigned b0, unsigned b1) {
    asm volatile("mma.sync.aligned.m16n8k16.row.col.f32.bf16.bf16.f32 "
                 "{%0,%1,%2,%3}, {%4,%5,%6,%7}, {%8,%9}, {%0,%1,%2,%3};"
                 : "+f"(c[0]), "+f"(c[1]), "+f"(c[2]), "+f"(c[3])
                 : "r"(a[0]), "r"(a[1]), "r"(a[2]), "r"(a[3]), "r"(b0), "r"(b1));
}
__device__ __forceinline__ uint32_t smem_u32(const void* p) {
    uint32_t a;
    asm("{ .reg .u64 t; cvta.to.shared.u64 t, %1; cvt.u32.u64 %0, t; }" : "=r"(a) : "l"(p));
    return a;
}
__device__ __forceinline__ void cp16(uint32_t saddr, const void* g) {
    asm volatile("cp.async.cg.shared.global [%0], [%1], 16;" :: "r"(saddr), "l"(g));
}
#define CP_COMMIT asm volatile("cp.async.commit_group;" ::: "memory")
#define CP_WAIT0  asm volatile("cp.async.wait_group 0;" ::: "memory")
__device__ __forceinline__ unsigned pack_bf(float lo, float hi) {
    unsigned r;
    asm("cvt.rn.bf16x2.f32 %0, %1, %2;" : "=r"(r) : "f"(hi), "f"(lo));
    return r;
}

// ---------------- GroupNorm --------------------------------------------------
__global__ void gn_stats(const float* __restrict__ x) {
    int bg = blockIdx.x;
    const float4* p = (const float4*)(x + (size_t)bg * GELEMS);
    float s = 0.f, ss = 0.f;
    for (int i = threadIdx.x; i < GELEMS/4; i += blockDim.x) {
        float4 v = p[i];
        s += v.x + v.y + v.z + v.w;
        ss += v.x*v.x + v.y*v.y + v.z*v.z + v.w*v.w;
    }
    __shared__ float rs[8], rss[8];
    #pragma unroll
    for (int o = 16; o; o >>= 1) { s += __shfl_down_sync(~0u, s, o); ss += __shfl_down_sync(~0u, ss, o); }
    if ((threadIdx.x & 31) == 0) { rs[threadIdx.x >> 5] = s; rss[threadIdx.x >> 5] = ss; }
    __syncthreads();
    if (threadIdx.x < 32) {
        s  = (threadIdx.x < 8) ? rs[threadIdx.x]  : 0.f;
        ss = (threadIdx.x < 8) ? rss[threadIdx.x] : 0.f;
        #pragma unroll
        for (int o = 4; o; o >>= 1) { s += __shfl_down_sync(~0u, s, o); ss += __shfl_down_sync(~0u, ss, o); }
        if (threadIdx.x == 0) {
            float mu = s / (float)GELEMS;
            float var = ss / (float)GELEMS - mu * mu;
            g_mu[bg] = mu; g_rs[bg] = rsqrtf(var + 1e-6f);
        }
    }
}

__global__ void gn_apply(const float* __restrict__ x, const float* __restrict__ gamma,
                         const float* __restrict__ beta) {
    __shared__ float tile[32][33];
    int b = blockIdx.z, c0 = blockIdx.y * 32, s0 = blockIdx.x * 32;
    int tx = threadIdx.x, ty = threadIdx.y;
    for (int i = ty; i < 32; i += 8) {
        int c = c0 + i, bg = b * NGRP + (c >> 3);
        float v = x[((size_t)(b * CCH + c)) * BHW + s0 + tx];
        tile[i][tx] = (v - g_mu[bg]) * g_rs[bg] * gamma[c] + beta[c];
    }
    __syncthreads();
    for (int i = ty; i < 32; i += 8)
        g_th[((size_t)(b * BHW + s0 + i)) * CCH + c0 + tx] = __float2half(tile[tx][i]);
}

// ---------------- weight pack ------------------------------------------------
__global__ void w_pack(const float* __restrict__ wq, const float* __restrict__ wk,
                       const float* __restrict__ wv, const float* __restrict__ wp) {
    int r = blockIdx.x, tid = threadIdx.x;
    const float* w = (r < 256) ? wq : (r < 512) ? wk : (r < 768) ? wv : wp;
    g_wh[(size_t)r * 256 + tid] = __float2half(w[(size_t)(r & 255) * 256 + tid]);
}

// ---------------- fp16 gemm core (K=256) -------------------------------------
__device__ __forceinline__ void gemm_core_h(const __half* A, const __half* B, int m0,
                                            __half* As, __half* Bs, float acc[2][8][4]) {
    const int tid = threadIdx.x, lane = tid & 31, warp = tid >> 5;
    const int wm = warp >> 1, wn = warp & 1, g = lane >> 2, t4 = lane & 3;
    #pragma unroll
    for (int mi = 0; mi < 2; mi++)
        #pragma unroll
        for (int ni = 0; ni < 8; ni++)
            #pragma unroll
            for (int e = 0; e < 4; e++) acc[mi][ni][e] = 0.f;
    for (int kc = 0; kc < 256; kc += 32) {
        #pragma unroll
        for (int it = 0; it < 2; it++) {
            int idx = tid + it * 256, row = idx >> 2, seg = idx & 3;
            *(float4*)(As + row * 40 + seg * 8) =
                *(const float4*)(A + (size_t)(m0 + row) * 256 + kc + seg * 8);
            *(float4*)(Bs + row * 40 + seg * 8) =
                *(const float4*)(B + (size_t)row * 256 + kc + seg * 8);
        }
        __syncthreads();
        #pragma unroll
        for (int k16 = 0; k16 < 2; k16++) {
            unsigned af[2][4];
            #pragma unroll
            for (int mi = 0; mi < 2; mi++) {
                int r = wm * 32 + mi * 16 + g;
                af[mi][0] = *(unsigned*)&As[r * 40 + k16*16 + t4*2];
                af[mi][1] = *(unsigned*)&As[(r + 8) * 40 + k16*16 + t4*2];
                af[mi][2] = *(unsigned*)&As[r * 40 + k16*16 + 8 + t4*2];
                af[mi][3] = *(unsigned*)&As[(r + 8) * 40 + k16*16 + 8 + t4*2];
            }
            #pragma unroll
            for (int ni = 0; ni < 8; ni++) {
                int cc = wn * 64 + ni * 8 + g;
                unsigned b0 = *(unsigned*)&Bs[cc * 40 + k16*16 + t4*2];
                unsigned b1 = *(unsigned*)&Bs[cc * 40 + k16*16 + 8 + t4*2];
                mma_f16(acc[0][ni], af[0], b0, b1);
                mma_f16(acc[1][ni], af[1], b0, b1);
            }
        }
        __syncthreads();
    }
}

// qkv: q,k -> fp16 (k scaled u/16); v -> bf16 token-pair packed
__global__ __launch_bounds__(256, 2)
void gemm_qkv(const float* __restrict__ bq, const float* __restrict__ bk,
              const float* __restrict__ bv) {
    const int n0 = blockIdx.x * 128, m0 = blockIdx.y * 128;
    const float* Bi = (n0 < 256) ? bq : (n0 < 512) ? bk : bv;
    __shared__ __align__(16) __half As[128 * 40];
    __shared__ __align__(16) __half Bs[128 * 40];
    float acc[2][8][4];
    gemm_core_h(g_th, g_wh + (size_t)n0 * 256, m0, As, Bs, acc);
    const int lane = threadIdx.x & 31, warp = threadIdx.x >> 5;
    const int wm = warp >> 1, wn = warp & 1, g = lane >> 2, t4 = lane & 3;
    #pragma unroll
    for (int mi = 0; mi < 2; mi++) {
        int rbase = m0 + wm * 32 + mi * 16 + g;
        #pragma unroll
        for (int ni = 0; ni < 8; ni++) {
            int cl = wn * 64 + ni * 8 + t4 * 2, cg = n0 + cl;
            #pragma unroll
            for (int half = 0; half < 2; half++) {
                int rr = rbase + half * 8;
                float v0 = acc[mi][ni][half * 2 + 0] + Bi[(n0 & 255) + cl];
                float v1 = acc[mi][ni][half * 2 + 1] + Bi[(n0 & 255) + cl + 1];
                if (cg < 512) {
                    if (cg >= 256) { float us = g_u[rr] * 0.0625f; v0 *= us; v1 *= us; }
                    *(__half2*)&g_qkh[(size_t)rr * 512 + cg] = __floats2half2_rn(v0, v1);
                } else {
                    int c2 = cg - 512, t2 = rr >> 1, par = rr & 1;
                    __nv_bfloat16* vb = (__nv_bfloat16*)g_vp;
                    vb[((size_t)t2 * 256 + c2) * 2 + par]     = __float2bfloat16(v0);
                    vb[((size_t)t2 * 256 + c2 + 1) * 2 + par] = __float2bfloat16(v1);
                }
            }
        }
    }
}

// proj transposed: out[b][c][s] = x + Wp @ O^T + bp
__global__ __launch_bounds__(256, 2)
void gemm_proj_t(const float* __restrict__ x, const float* __restrict__ bias,
                 float* __restrict__ out) {
    const int n0 = blockIdx.x * 128;
    const int m0 = blockIdx.y * 128;
    __shared__ __align__(16) __half As[128 * 40];
    __shared__ __align__(16) __half Bs[128 * 40];
    float acc[2][8][4];
    gemm_core_h(g_wh + (size_t)768 * 256, g_oh + (size_t)n0 * 256, m0, As, Bs, acc);
    const int lane = threadIdx.x & 31, warp = threadIdx.x >> 5;
    const int wm = warp >> 1, wn = warp & 1, g = lane >> 2, t4 = lane & 3;
    #pragma unroll
    for (int mi = 0; mi < 2; mi++) {
        int chb = m0 + wm * 32 + mi * 16 + g;
        #pragma unroll
        for (int ni = 0; ni < 8; ni++) {
            int tok = n0 + wn * 64 + ni * 8 + t4 * 2;
            int bb = tok >> 12, s = tok & 4095;
            #pragma unroll
            for (int half = 0; half < 2; half++) {
                int ch = chb + half * 8;
                size_t idx = ((size_t)(bb * CCH + ch)) * BHW + s;
                float2 xv = *(const float2*)(x + idx);
                *(float2*)(out + idx) =
                    make_float2(acc[mi][ni][half * 2 + 0] + bias[ch] + xv.x,
                                acc[mi][ni][half * 2 + 1] + bias[ch] + xv.y);
            }
        }
    }
}

// ---------------- u = sigmoid(t @ wu^T + bu) ---------------------------------
__global__ void u_kernel(const float* __restrict__ wu, const float* __restrict__ bu,
                         float* __restrict__ dout_u) {
    int i = blockIdx.x * 8 + (threadIdx.x >> 5);
    int lane = threadIdx.x & 31;
    const __half2* t2 = (const __half2*)(g_th + (size_t)i * CCH);
    float s = 0.f;
    #pragma unroll
    for (int j = 0; j < 4; j++) {
        float2 f = __half22float2(t2[lane + j * 32]);
        int c = (lane + j * 32) * 2;
        s += f.x * wu[c] + f.y * wu[c + 1];
    }
    #pragma unroll
    for (int o = 16; o; o >>= 1) s += __shfl_down_sync(~0u, s, o);
    if (lane == 0) {
        float uu = 1.f / (1.f + expf(-(s + bu[0])));
        g_u[i] = uu; dout_u[i] = uu;
    }
}

// -------- flash7: BN=64, 16 warps = 4 QK + 8 PV + 4 loaders ------------------
__global__ __launch_bounds__(512, 1)
void flash7(float* __restrict__ unused) {
    extern __shared__ __align__(16) char dsmb[];
    float* dsm = (float*)dsmb;
    uint32_t sb = smem_u32(dsmb);
    int b = blockIdx.y, q0 = blockIdx.x * 64;
    int tid = threadIdx.x, lane = tid & 31, warp = tid >> 5;
    int g = lane >> 2, t4 = lane & 3;
    size_t tokb = (size_t)b * BHW;
    const __half* Qg = g_qkh + (tokb + q0) * 512;
    const __half* Kg = g_qkh + tokb * 512 + 256;
    const unsigned* Vg = g_vp + (size_t)b * 2048 * 256;

    // stage Q (overlaps V0), read frags, release
    for (int i = tid; i < 2048; i += 512) {
        int r = i >> 5, c8 = i & 31;
        cp16(sb + QSTGB + r * 528 + c8 * 16, Qg + (size_t)r * 512 + c8 * 8);
    }
    CP_COMMIT; CP_WAIT0; __syncthreads();

    float rp[64];   // QK warps: Q frags. PV warps: O accumulator.
    if (warp < 4) {
        int r0 = warp * 16 + g;
        const __half* q = (const __half*)(dsmb + QSTGB);
        #pragma unroll
        for (int k16 = 0; k16 < 16; k16++) {
            rp[k16*4+0] = __uint_as_float(*(const unsigned*)&q[r0 * 264 + k16*16 + t4*2]);
            rp[k16*4+1] = __uint_as_float(*(const unsigned*)&q[(r0+8) * 264 + k16*16 + t4*2]);
            rp[k16*4+2] = __uint_as_float(*(const unsigned*)&q[r0 * 264 + k16*16 + 8 + t4*2]);
            rp[k16*4+3] = __uint_as_float(*(const unsigned*)&q[(r0+8) * 264 + k16*16 + 8 + t4*2]);
        }
    } else {
        #pragma unroll
        for (int j = 0; j < 64; j++) rp[j] = 0.f;
    }
    __syncthreads();

    for (int i = tid; i < 2048; i += 512) {          // K(0) [64][264h]
        int r = i >> 5, c8 = i & 31;
        cp16(sb + KB(0) + r * 528 + c8 * 16, Kg + (size_t)r * 512 + c8 * 8);
    }
    for (int i = tid; i < 2048; i += 512) {          // V(0) [32][264]u32
        int r = i >> 6, c4 = (i & 63) * 4;
        cp16(sb + VB(0) + r * 1056 + c4 * 4, Vg + (size_t)r * 256 + c4);
    }
    CP_COMMIT;

    int pw = warp - 4, wm = pw & 3, wn = pw >> 2;
    float lac0 = 0.f, lac1 = 0.f;

    for (int it = 0; it <= FITERS; ++it) {
        CP_WAIT0; __syncthreads();
        if (warp >= 12) {                            // loaders
            if (it + 1 < FITERS) {
                int t2 = tid - 384;
                const __half* kn = Kg + (size_t)(it + 1) * 64 * 512;
                const unsigned* vn = Vg + (size_t)(it + 1) * 32 * 256;
                uint32_t kd = sb + KB((it + 1) & 1), vd = sb + VB((it + 1) % 3);
                for (int i = t2; i < 2048; i += 128) {
                    int r = i >> 5, c8 = i & 31;
                    cp16(kd + r * 528 + c8 * 16, kn + (size_t)r * 512 + c8 * 8);
                }
                for (int i = t2; i < 2048; i += 128) {
                    int r = i >> 6, c4 = (i & 63) * 4;
                    cp16(vd + r * 1056 + c4 * 4, vn + (size_t)r * 256 + c4);
                }
                CP_COMMIT;
            }
        } else if (warp < 4) {                       // QK + exp + P pack
            if (it < FITERS) {
                const __half* kb = (const __half*)(dsmb + KB(it & 1));
                float sacc[8][4];
                #pragma unroll
                for (int ni = 0; ni < 8; ni++)
                    #pragma unroll
                    for (int e = 0; e < 4; e++) sacc[ni][e] = 0.f;
                #pragma unroll
                for (int k16 = 0; k16 < 16; k16++) {
                    unsigned af[4] = { fu(rp[k16*4]), fu(rp[k16*4+1]), fu(rp[k16*4+2]), fu(rp[k16*4+3]) };
                    #pragma unroll
                    for (int ni = 0; ni < 8; ni++) {
                        int c = ni * 8 + g;
                        unsigned b0 = *(const unsigned*)&kb[c * 264 + k16*16 + t4*2];
                        unsigned b1 = *(const unsigned*)&kb[c * 264 + k16*16 + 8 + t4*2];
                        mma_f16(sacc[ni], af, b0, b1);
                    }
                }
                unsigned* P = (unsigned*)(dsmb + PB(it & 1));
                int r0 = warp * 16 + g;
                #pragma unroll
                for (int ni = 0; ni < 8; ni++) {
                    float e0 = __expf(sacc[ni][0]), e1 = __expf(sacc[ni][1]);
                    float e2 = __expf(sacc[ni][2]), e3 = __expf(sacc[ni][3]);
                    lac0 += e0 + e1; lac1 += e2 + e3;
                    P[r0 * 40 + ni*4 + t4]       = pack_bf(e0, e1);
                    P[(r0 + 8) * 40 + ni*4 + t4] = pack_bf(e2, e3);
                }
            }
        } else {                                     // PV (8 warps)
            if (it >= 1) {
                int pit = it - 1;
                const unsigned* P = (const unsigned*)(dsmb + PB(pit & 1));
                const unsigned* V = (const unsigned*)(dsmb + VB(pit % 3));
                int m0 = wm * 16;
                #pragma unroll
                for (int k16 = 0; k16 < 4; k16++) {
                    unsigned a[4] = {
                        P[(m0 + g) * 40 + k16*8 + t4],
                        P[(m0 + 8 + g) * 40 + k16*8 + t4],
                        P[(m0 + g) * 40 + k16*8 + 4 + t4],
                        P[(m0 + 8 + g) * 40 + k16*8 + 4 + t4] };
                    #pragma unroll
                    for (int ni = 0; ni < 16; ni++) {
                        int c = wn * 128 + ni * 8 + g;
                        unsigned b0 = V[(k16*8 + t4) * 264 + c];
                        unsigned b1 = V[(k16*8 + 4 + t4) * 264 + c];
                        mma_bf16(&rp[ni*4], a, b0, b1);
                    }
                }
            }
        }
    }

    if (warp < 4) {
        lac0 += __shfl_xor_sync(~0u, lac0, 1);
        lac0 += __shfl_xor_sync(~0u, lac0, 2);
        lac1 += __shfl_xor_sync(~0u, lac1, 1);
        lac1 += __shfl_xor_sync(~0u, lac1, 2);
        if (t4 == 0) {
            dsm[SLB/4 + warp*16 + g]     = lac0;
            dsm[SLB/4 + warp*16 + g + 8] = lac1;
        }
    }
    __syncthreads();
    if (warp >= 4 && warp < 12) {
        int r = wm * 16 + g;
        float i0 = 1.f / dsm[SLB/4 + r];
        float i1 = 1.f / dsm[SLB/4 + r + 8];
        __half* o0 = g_oh + (tokb + q0 + r) * 256;
        __half* o1 = g_oh + (tokb + q0 + r + 8) * 256;
        #pragma unroll
        for (int ni = 0; ni < 16; ni++) {
            int cc = wn * 128 + ni * 8 + t4 * 2;
            *(__half2*)&o0[cc] = __floats2half2_rn(rp[ni*4] * i0,   rp[ni*4+1] * i0);
            *(__half2*)&o1[cc] = __floats2half2_rn(rp[ni*4+2] * i1, rp[ni*4+3] * i1);
        }
    }
    (void)unused;
}

// ---------------- launch -----------------------------------------------------
extern "C" void kernel_launch(void* const* d_in, const int* in_sizes, int n_in,
                              void* d_out, int out_size) {
    (void)in_sizes; (void)n_in; (void)out_size;
    const float* x     = (const float*)d_in[0];
    const float* gamma = (const float*)d_in[1];
    const float* beta  = (const float*)d_in[2];
    const float* wq = (const float*)d_in[3],  *bq = (const float*)d_in[4];
    const float* wk = (const float*)d_in[5],  *bk = (const float*)d_in[6];
    const float* wv = (const float*)d_in[7],  *bv = (const float*)d_in[8];
    const float* wu = (const float*)d_in[9],  *bu = (const float*)d_in[10];
    const float* wp = (const float*)d_in[11], *bp = (const float*)d_in[12];
    float* out = (float*)d_out;

    cudaFuncSetAttribute(flash7, cudaFuncAttributeMaxDynamicSharedMemorySize, FSMEM);

    // order chosen so ncu (-s 5 -c 1) captures flash7
    w_pack<<<1024, 256>>>(wq, wk, wv, wp);
    gn_stats<<<NBAT * NGRP, 256>>>(x);
    gn_apply<<<dim3(BHW / 32, CCH / 32, NBAT), dim3(32, 8)>>>(x, gamma, beta);
    u_kernel<<<NTOK / 8, 256>>>(wu, bu, out + OUT_MAIN);
    gemm_qkv<<<dim3(6, 128), 256>>>(bq, bk, bv);
    flash7<<<dim3(BHW / 64, NBAT), 512, FSMEM>>>(out);
    gemm_proj_t<<<dim3(128, 2), 256>>>(x, bp, out);
}

// round 16
// speedup vs baseline: 1.2970x; 1.0239x over previous
#include <cuda_runtime.h>
#include <cuda_bf16.h>
#include <cuda_fp16.h>
#include <stdint.h>

#define BHW   4096
#define CCH   256
#define NBAT  4
#define NTOK  16384
#define NGRP  32
#define GELEMS (8*BHW)
#define OUT_MAIN ((size_t)NBAT*CCH*BHW)

#define FITERS 64
// flash smem BYTE offsets (BN=64)
#define KB(i)  ((i)*33792)
#define VB(j)  (67584 + (j)*33792)
#define PB(p)  (169344 + (p)*10240)
#define SLB    189824
#define QSTGB  67584
#define FSMEM  190080

__device__ __half   g_th[(size_t)NTOK*CCH];
__device__ __half   g_qkh[(size_t)NTOK*512];
__device__ unsigned g_vp[(size_t)(NTOK/2)*256];
__device__ __half   g_oh[(size_t)NTOK*CCH];
__device__ __half   g_wh[(size_t)1024*256];
__device__ float    g_u[NTOK];
__device__ float    g_mu[NBAT*NGRP];
__device__ float    g_rs[NBAT*NGRP];
__device__ float    g_ps[512*2];

__device__ __forceinline__ unsigned fu(float f) { return __float_as_uint(f); }
__device__ __forceinline__ void mma_f16(float* c, const unsigned* a, unsigned b0, unsigned b1) {
    asm volatile("mma.sync.aligned.m16n8k16.row.col.f32.f16.f16.f32 "
                 "{%0,%1,%2,%3}, {%4,%5,%6,%7}, {%8,%9}, {%0,%1,%2,%3};"
                 : "+f"(c[0]), "+f"(c[1]), "+f"(c[2]), "+f"(c[3])
                 : "r"(a[0]), "r"(a[1]), "r"(a[2]), "r"(a[3]), "r"(b0), "r"(b1));
}
__device__ __forceinline__ void mma_bf16(float* c, const unsigned* a, unsigned b0, unsigned b1) {
    asm volatile("mma.sync.aligned.m16n8k16.row.col.f32.bf16.bf16.f32 "
                 "{%0,%1,%2,%3}, {%4,%5,%6,%7}, {%8,%9}, {%0,%1,%2,%3};"
                 : "+f"(c[0]), "+f"(c[1]), "+f"(c[2]), "+f"(c[3])
                 : "r"(a[0]), "r"(a[1]), "r"(a[2]), "r"(a[3]), "r"(b0), "r"(b1));
}
__device__ __forceinline__ uint32_t smem_u32(const void* p) {
    uint32_t a;
    asm("{ .reg .u64 t; cvta.to.shared.u64 t, %1; cvt.u32.u64 %0, t; }" : "=r"(a) : "l"(p));
    return a;
}
__device__ __forceinline__ void cp16(uint32_t saddr, const void* g) {
    asm volatile("cp.async.cg.shared.global [%0], [%1], 16;" :: "r"(saddr), "l"(g));
}
#define CP_COMMIT asm volatile("cp.async.commit_group;" ::: "memory")
#define CP_WAIT0  asm volatile("cp.async.wait_group 0;" ::: "memory")
__device__ __forceinline__ unsigned pack_bf(float lo, float hi) {
    unsigned r;
    asm("cvt.rn.bf16x2.f32 %0, %1, %2;" : "=r"(r) : "f"(hi), "f"(lo));
    return r;
}

// ---------------- GroupNorm (two-stage stats) --------------------------------
__global__ void gn_stats1(const float* __restrict__ x) {
    int cta = blockIdx.x;                 // 512 CTAs; 4 per (b,g); 8192 elems each
    const float4* p = (const float4*)(x + (size_t)cta * 8192);
    float s = 0.f, ss = 0.f;
    for (int i = threadIdx.x; i < 2048; i += 256) {
        float4 v = p[i];
        s += v.x + v.y + v.z + v.w;
        ss += v.x*v.x + v.y*v.y + v.z*v.z + v.w*v.w;
    }
    __shared__ float rs[8], rss[8];
    #pragma unroll
    for (int o = 16; o; o >>= 1) { s += __shfl_down_sync(~0u, s, o); ss += __shfl_down_sync(~0u, ss, o); }
    if ((threadIdx.x & 31) == 0) { rs[threadIdx.x >> 5] = s; rss[threadIdx.x >> 5] = ss; }
    __syncthreads();
    if (threadIdx.x < 32) {
        s  = (threadIdx.x < 8) ? rs[threadIdx.x]  : 0.f;
        ss = (threadIdx.x < 8) ? rss[threadIdx.x] : 0.f;
        #pragma unroll
        for (int o = 4; o; o >>= 1) { s += __shfl_down_sync(~0u, s, o); ss += __shfl_down_sync(~0u, ss, o); }
        if (threadIdx.x == 0) { g_ps[cta*2] = s; g_ps[cta*2 + 1] = ss; }
    }
}
__global__ void gn_stats2() {
    int bg = threadIdx.x;                 // 128 threads, 1 CTA
    float s = 0.f, ss = 0.f;
    #pragma unroll
    for (int j = 0; j < 4; j++) { s += g_ps[(bg*4 + j)*2]; ss += g_ps[(bg*4 + j)*2 + 1]; }
    float mu = s / (float)GELEMS;
    float var = ss / (float)GELEMS - mu * mu;
    g_mu[bg] = mu; g_rs[bg] = rsqrtf(var + 1e-6f);
}

__global__ void gn_apply(const float* __restrict__ x, const float* __restrict__ gamma,
                         const float* __restrict__ beta) {
    __shared__ float tile[32][33];
    int b = blockIdx.z, c0 = blockIdx.y * 32, s0 = blockIdx.x * 32;
    int tx = threadIdx.x, ty = threadIdx.y;
    for (int i = ty; i < 32; i += 8) {
        int c = c0 + i, bg = b * NGRP + (c >> 3);
        float v = x[((size_t)(b * CCH + c)) * BHW + s0 + tx];
        tile[i][tx] = (v - g_mu[bg]) * g_rs[bg] * gamma[c] + beta[c];
    }
    __syncthreads();
    for (int i = ty; i < 32; i += 8)
        g_th[((size_t)(b * BHW + s0 + i)) * CCH + c0 + tx] = __float2half(tile[tx][i]);
}

// ---------------- weight pack ------------------------------------------------
__global__ void w_pack(const float* __restrict__ wq, const float* __restrict__ wk,
                       const float* __restrict__ wv, const float* __restrict__ wp) {
    int r = blockIdx.x, tid = threadIdx.x;
    const float* w = (r < 256) ? wq : (r < 512) ? wk : (r < 768) ? wv : wp;
    g_wh[(size_t)r * 256 + tid] = __float2half(w[(size_t)(r & 255) * 256 + tid]);
}

// --------- fp16 gemm core, cp.async double-buffered (K=256) ------------------
__device__ __forceinline__ void gemm_core_h(const __half* A, const __half* B, int m0,
                                            __half* As, __half* Bs, float acc[2][8][4]) {
    const int tid = threadIdx.x, lane = tid & 31, warp = tid >> 5;
    const int wm = warp >> 1, wn = warp & 1, g = lane >> 2, t4 = lane & 3;
    uint32_t sa = smem_u32(As), sbb = smem_u32(Bs);
    #pragma unroll
    for (int mi = 0; mi < 2; mi++)
        #pragma unroll
        for (int ni = 0; ni < 8; ni++)
            #pragma unroll
            for (int e = 0; e < 4; e++) acc[mi][ni][e] = 0.f;

    // stage 0 loads
    #pragma unroll
    for (int it = 0; it < 2; it++) {
        int i = tid + it * 256, row = i >> 2, seg = i & 3;
        cp16(sa  + row * 80 + seg * 16, A + (size_t)(m0 + row) * 256 + seg * 8);
        cp16(sbb + row * 80 + seg * 16, B + (size_t)row * 256 + seg * 8);
    }
    CP_COMMIT;

    for (int kc8 = 0; kc8 < 8; kc8++) {
        CP_WAIT0; __syncthreads();
        if (kc8 + 1 < 8) {
            int kc = (kc8 + 1) * 32, buf = ((kc8 + 1) & 1) * 10240;  // bytes
            #pragma unroll
            for (int it = 0; it < 2; it++) {
                int i = tid + it * 256, row = i >> 2, seg = i & 3;
                cp16(sa  + buf + row * 80 + seg * 16, A + (size_t)(m0 + row) * 256 + kc + seg * 8);
                cp16(sbb + buf + row * 80 + seg * 16, B + (size_t)row * 256 + kc + seg * 8);
            }
            CP_COMMIT;
        }
        const __half* Ab = As + (kc8 & 1) * 5120;
        const __half* Bb = Bs + (kc8 & 1) * 5120;
        #pragma unroll
        for (int k16 = 0; k16 < 2; k16++) {
            unsigned af[2][4];
            #pragma unroll
            for (int mi = 0; mi < 2; mi++) {
                int r = wm * 32 + mi * 16 + g;
                af[mi][0] = *(unsigned*)&Ab[r * 40 + k16*16 + t4*2];
                af[mi][1] = *(unsigned*)&Ab[(r + 8) * 40 + k16*16 + t4*2];
                af[mi][2] = *(unsigned*)&Ab[r * 40 + k16*16 + 8 + t4*2];
                af[mi][3] = *(unsigned*)&Ab[(r + 8) * 40 + k16*16 + 8 + t4*2];
            }
            #pragma unroll
            for (int ni = 0; ni < 8; ni++) {
                int cc = wn * 64 + ni * 8 + g;
                unsigned b0 = *(unsigned*)&Bb[cc * 40 + k16*16 + t4*2];
                unsigned b1 = *(unsigned*)&Bb[cc * 40 + k16*16 + 8 + t4*2];
                mma_f16(acc[0][ni], af[0], b0, b1);
                mma_f16(acc[1][ni], af[1], b0, b1);
            }
        }
    }
}

// qkv: q,k -> fp16 (k scaled u/16); v -> bf16 token-pair packed
__global__ __launch_bounds__(256, 2)
void gemm_qkv(const float* __restrict__ bq, const float* __restrict__ bk,
              const float* __restrict__ bv) {
    const int n0 = blockIdx.x * 128, m0 = blockIdx.y * 128;
    const float* Bi = (n0 < 256) ? bq : (n0 < 512) ? bk : bv;
    __shared__ __align__(16) __half As[2 * 5120];
    __shared__ __align__(16) __half Bs[2 * 5120];
    float acc[2][8][4];
    gemm_core_h(g_th, g_wh + (size_t)n0 * 256, m0, As, Bs, acc);
    const int lane = threadIdx.x & 31, warp = threadIdx.x >> 5;
    const int wm = warp >> 1, wn = warp & 1, g = lane >> 2, t4 = lane & 3;
    #pragma unroll
    for (int mi = 0; mi < 2; mi++) {
        int rbase = m0 + wm * 32 + mi * 16 + g;
        #pragma unroll
        for (int ni = 0; ni < 8; ni++) {
            int cl = wn * 64 + ni * 8 + t4 * 2, cg = n0 + cl;
            #pragma unroll
            for (int half = 0; half < 2; half++) {
                int rr = rbase + half * 8;
                float v0 = acc[mi][ni][half * 2 + 0] + Bi[(n0 & 255) + cl];
                float v1 = acc[mi][ni][half * 2 + 1] + Bi[(n0 & 255) + cl + 1];
                if (cg < 512) {
                    if (cg >= 256) { float us = g_u[rr] * 0.0625f; v0 *= us; v1 *= us; }
                    *(__half2*)&g_qkh[(size_t)rr * 512 + cg] = __floats2half2_rn(v0, v1);
                } else {
                    int c2 = cg - 512, t2 = rr >> 1, par = rr & 1;
                    __nv_bfloat16* vb = (__nv_bfloat16*)g_vp;
                    vb[((size_t)t2 * 256 + c2) * 2 + par]     = __float2bfloat16(v0);
                    vb[((size_t)t2 * 256 + c2 + 1) * 2 + par] = __float2bfloat16(v1);
                }
            }
        }
    }
}

// proj transposed: out[b][c][s] = x + Wp @ O^T + bp
__global__ __launch_bounds__(256, 2)
void gemm_proj_t(const float* __restrict__ x, const float* __restrict__ bias,
                 float* __restrict__ out) {
    const int n0 = blockIdx.x * 128;
    const int m0 = blockIdx.y * 128;
    __shared__ __align__(16) __half As[2 * 5120];
    __shared__ __align__(16) __half Bs[2 * 5120];
    float acc[2][8][4];
    gemm_core_h(g_wh + (size_t)768 * 256, g_oh + (size_t)n0 * 256, m0, As, Bs, acc);
    const int lane = threadIdx.x & 31, warp = threadIdx.x >> 5;
    const int wm = warp >> 1, wn = warp & 1, g = lane >> 2, t4 = lane & 3;
    #pragma unroll
    for (int mi = 0; mi < 2; mi++) {
        int chb = m0 + wm * 32 + mi * 16 + g;
        #pragma unroll
        for (int ni = 0; ni < 8; ni++) {
            int tok = n0 + wn * 64 + ni * 8 + t4 * 2;
            int bb = tok >> 12, s = tok & 4095;
            #pragma unroll
            for (int half = 0; half < 2; half++) {
                int ch = chb + half * 8;
                size_t idx = ((size_t)(bb * CCH + ch)) * BHW + s;
                float2 xv = *(const float2*)(x + idx);
                *(float2*)(out + idx) =
                    make_float2(acc[mi][ni][half * 2 + 0] + bias[ch] + xv.x,
                                acc[mi][ni][half * 2 + 1] + bias[ch] + xv.y);
            }
        }
    }
}

// ---------------- u = sigmoid(t @ wu^T + bu) ---------------------------------
__global__ void u_kernel(const float* __restrict__ wu, const float* __restrict__ bu,
                         float* __restrict__ dout_u) {
    int i = blockIdx.x * 8 + (threadIdx.x >> 5);
    int lane = threadIdx.x & 31;
    const __half2* t2 = (const __half2*)(g_th + (size_t)i * CCH);
    float s = 0.f;
    #pragma unroll
    for (int j = 0; j < 4; j++) {
        float2 f = __half22float2(t2[lane + j * 32]);
        int c = (lane + j * 32) * 2;
        s += f.x * wu[c] + f.y * wu[c + 1];
    }
    #pragma unroll
    for (int o = 16; o; o >>= 1) s += __shfl_down_sync(~0u, s, o);
    if (lane == 0) {
        float uu = 1.f / (1.f + expf(-(s + bu[0])));
        g_u[i] = uu; dout_u[i] = uu;
    }
}

// -------- flash7: BN=64, 16 warps = 4 QK + 8 PV + 4 loaders ------------------
__global__ __launch_bounds__(512, 1)
void flash7(float* __restrict__ unused) {
    extern __shared__ __align__(16) char dsmb[];
    float* dsm = (float*)dsmb;
    uint32_t sb = smem_u32(dsmb);
    int b = blockIdx.y, q0 = blockIdx.x * 64;
    int tid = threadIdx.x, lane = tid & 31, warp = tid >> 5;
    int g = lane >> 2, t4 = lane & 3;
    size_t tokb = (size_t)b * BHW;
    const __half* Qg = g_qkh + (tokb + q0) * 512;
    const __half* Kg = g_qkh + tokb * 512 + 256;
    const unsigned* Vg = g_vp + (size_t)b * 2048 * 256;

    for (int i = tid; i < 2048; i += 512) {
        int r = i >> 5, c8 = i & 31;
        cp16(sb + QSTGB + r * 528 + c8 * 16, Qg + (size_t)r * 512 + c8 * 8);
    }
    CP_COMMIT; CP_WAIT0; __syncthreads();

    float rp[64];
    if (warp < 4) {
        int r0 = warp * 16 + g;
        const __half* q = (const __half*)(dsmb + QSTGB);
        #pragma unroll
        for (int k16 = 0; k16 < 16; k16++) {
            rp[k16*4+0] = __uint_as_float(*(const unsigned*)&q[r0 * 264 + k16*16 + t4*2]);
            rp[k16*4+1] = __uint_as_float(*(const unsigned*)&q[(r0+8) * 264 + k16*16 + t4*2]);
            rp[k16*4+2] = __uint_as_float(*(const unsigned*)&q[r0 * 264 + k16*16 + 8 + t4*2]);
            rp[k16*4+3] = __uint_as_float(*(const unsigned*)&q[(r0+8) * 264 + k16*16 + 8 + t4*2]);
        }
    } else {
        #pragma unroll
        for (int j = 0; j < 64; j++) rp[j] = 0.f;
    }
    __syncthreads();

    for (int i = tid; i < 2048; i += 512) {
        int r = i >> 5, c8 = i & 31;
        cp16(sb + KB(0) + r * 528 + c8 * 16, Kg + (size_t)r * 512 + c8 * 8);
    }
    for (int i = tid; i < 2048; i += 512) {
        int r = i >> 6, c4 = (i & 63) * 4;
        cp16(sb + VB(0) + r * 1056 + c4 * 4, Vg + (size_t)r * 256 + c4);
    }
    CP_COMMIT;

    int pw = warp - 4, wm = pw & 3, wn = pw >> 2;
    float lac0 = 0.f, lac1 = 0.f;

    for (int it = 0; it <= FITERS; ++it) {
        CP_WAIT0; __syncthreads();
        if (warp >= 12) {
            if (it + 1 < FITERS) {
                int t2 = tid - 384;
                const __half* kn = Kg + (size_t)(it + 1) * 64 * 512;
                const unsigned* vn = Vg + (size_t)(it + 1) * 32 * 256;
                uint32_t kd = sb + KB((it + 1) & 1), vd = sb + VB((it + 1) % 3);
                for (int i = t2; i < 2048; i += 128) {
                    int r = i >> 5, c8 = i & 31;
                    cp16(kd + r * 528 + c8 * 16, kn + (size_t)r * 512 + c8 * 8);
                }
                for (int i = t2; i < 2048; i += 128) {
                    int r = i >> 6, c4 = (i & 63) * 4;
                    cp16(vd + r * 1056 + c4 * 4, vn + (size_t)r * 256 + c4);
                }
                CP_COMMIT;
            }
        } else if (warp < 4) {
            if (it < FITERS) {
                const __half* kb = (const __half*)(dsmb + KB(it & 1));
                float sacc[8][4];
                #pragma unroll
                for (int ni = 0; ni < 8; ni++)
                    #pragma unroll
                    for (int e = 0; e < 4; e++) sacc[ni][e] = 0.f;
                #pragma unroll
                for (int k16 = 0; k16 < 16; k16++) {
                    unsigned af[4] = { fu(rp[k16*4]), fu(rp[k16*4+1]), fu(rp[k16*4+2]), fu(rp[k16*4+3]) };
                    #pragma unroll
                    for (int ni = 0; ni < 8; ni++) {
                        int c = ni * 8 + g;
                        unsigned b0 = *(const unsigned*)&kb[c * 264 + k16*16 + t4*2];
                        unsigned b1 = *(const unsigned*)&kb[c * 264 + k16*16 + 8 + t4*2];
                        mma_f16(sacc[ni], af, b0, b1);
                    }
                }
                unsigned* P = (unsigned*)(dsmb + PB(it & 1));
                int r0 = warp * 16 + g;
                #pragma unroll
                for (int ni = 0; ni < 8; ni++) {
                    float e0 = __expf(sacc[ni][0]), e1 = __expf(sacc[ni][1]);
                    float e2 = __expf(sacc[ni][2]), e3 = __expf(sacc[ni][3]);
                    lac0 += e0 + e1; lac1 += e2 + e3;
                    P[r0 * 40 + ni*4 + t4]       = pack_bf(e0, e1);
                    P[(r0 + 8) * 40 + ni*4 + t4] = pack_bf(e2, e3);
                }
            }
        } else {
            if (it >= 1) {
                int pit = it - 1;
                const unsigned* P = (const unsigned*)(dsmb + PB(pit & 1));
                const unsigned* V = (const unsigned*)(dsmb + VB(pit % 3));
                int m0 = wm * 16;
                #pragma unroll
                for (int k16 = 0; k16 < 4; k16++) {
                    unsigned a[4] = {
                        P[(m0 + g) * 40 + k16*8 + t4],
                        P[(m0 + 8 + g) * 40 + k16*8 + t4],
                        P[(m0 + g) * 40 + k16*8 + 4 + t4],
                        P[(m0 + 8 + g) * 40 + k16*8 + 4 + t4] };
                    #pragma unroll
                    for (int ni = 0; ni < 16; ni++) {
                        int c = wn * 128 + ni * 8 + g;
                        unsigned b0 = V[(k16*8 + t4) * 264 + c];
                        unsigned b1 = V[(k16*8 + 4 + t4) * 264 + c];
                        mma_bf16(&rp[ni*4], a, b0, b1);
                    }
                }
            }
        }
    }

    if (warp < 4) {
        lac0 += __shfl_xor_sync(~0u, lac0, 1);
        lac0 += __shfl_xor_sync(~0u, lac0, 2);
        lac1 += __shfl_xor_sync(~0u, lac1, 1);
        lac1 += __shfl_xor_sync(~0u, lac1, 2);
        if (t4 == 0) {
            dsm[SLB/4 + warp*16 + g]     = lac0;
            dsm[SLB/4 + warp*16 + g + 8] = lac1;
        }
    }
    __syncthreads();
    if (warp >= 4 && warp < 12) {
        int r = wm * 16 + g;
        float i0 = 1.f / dsm[SLB/4 + r];
        float i1 = 1.f / dsm[SLB/4 + r + 8];
        __half* o0 = g_oh + (tokb + q0 + r) * 256;
        __half* o1 = g_oh + (tokb + q0 + r + 8) * 256;
        #pragma unroll
        for (int ni = 0; ni < 16; ni++) {
            int cc = wn * 128 + ni * 8 + t4 * 2;
            *(__half2*)&o0[cc] = __floats2half2_rn(rp[ni*4] * i0,   rp[ni*4+1] * i0);
            *(__half2*)&o1[cc] = __floats2half2_rn(rp[ni*4+2] * i1, rp[ni*4+3] * i1);
        }
    }
    (void)unused;
}

// ---------------- launch -----------------------------------------------------
extern "C" void kernel_launch(void* const* d_in, const int* in_sizes, int n_in,
                              void* d_out, int out_size) {
    (void)in_sizes; (void)n_in; (void)out_size;
    const float* x     = (const float*)d_in[0];
    const float* gamma = (const float*)d_in[1];
    const float* beta  = (const float*)d_in[2];
    const float* wq = (const float*)d_in[3],  *bq = (const float*)d_in[4];
    const float* wk = (const float*)d_in[5],  *bk = (const float*)d_in[6];
    const float* wv = (const float*)d_in[7],  *bv = (const float*)d_in[8];
    const float* wu = (const float*)d_in[9],  *bu = (const float*)d_in[10];
    const float* wp = (const float*)d_in[11], *bp = (const float*)d_in[12];
    float* out = (float*)d_out;

    cudaFuncSetAttribute(flash7, cudaFuncAttributeMaxDynamicSharedMemorySize, FSMEM);

    w_pack<<<1024, 256>>>(wq, wk, wv, wp);
    gn_stats1<<<512, 256>>>(x);
    gn_stats2<<<1, 128>>>();
    gn_apply<<<dim3(BHW / 32, CCH / 32, NBAT), dim3(32, 8)>>>(x, gamma, beta);
    u_kernel<<<NTOK / 8, 256>>>(wu, bu, out + OUT_MAIN);
    gemm_qkv<<<dim3(6, 128), 256>>>(bq, bk, bv);
    flash7<<<dim3(BHW / 64, NBAT), 512, FSMEM>>>(out);
    gemm_proj_t<<<dim3(128, 2), 256>>>(x, bp, out);
}